// round 15
// baseline (speedup 1.0000x reference)
#include <cuda_runtime.h>
#include <cuda_fp16.h>
#include <cstdint>

#define N_GENES 20000
#define UNITS   10000
#define DEG     32
#define BATCH   128

// |feature| transposed to [gene][batch] in fp16: 5.12 MB, L2-resident.
// Row = 256B; each (unit, deg) gather reads one full row, coalesced.
// The gather sits at the L2 slice-service floor (10.8-11.2us node,
// invariant across R4-R14 restructurings). Sub-fp16 storage fails the
// 1e-3 error gate (int8/row-scale ~1.2e-3); bytes are irreducible.
__device__ __half g_featT[(size_t)N_GENES * BATCH];

// ---------------------------------------------------------------------------
// K1: transpose + fabs + fp16.  feature [128, 20000] -> featT [N, B].
// One CTA per 32-gene column block covering the FULL batch: each gene's
// 256B featT row is written contiguously by one 64-thread group.
// ---------------------------------------------------------------------------
__global__ void __launch_bounds__(256) transpose_abs_kernel(
    const float* __restrict__ feature)
{
    __shared__ float tile[BATCH][33];            // tile[batch][gene], 16.9 KB
    const int gx  = blockIdx.x * 32;
    const int tx  = threadIdx.x & 31;            // gene within block
    const int row = threadIdx.x >> 5;            // batch row 0..7

#pragma unroll
    for (int k = 0; k < BATCH; k += 8)
        tile[row + k][tx] = fabsf(feature[(size_t)(row + k) * N_GENES + (gx + tx)]);
    __syncthreads();

    // 64 consecutive threads emit one contiguous 256B gene row.
#pragma unroll
    for (int tt = 0; tt < 8; tt++) {
        const int task = tt * 256 + threadIdx.x;
        const int g_l  = task >> 6;              // 0..31
        const int p    = task & 63;              // batch pair
        const __half2 h = __floats2half2_rn(tile[2 * p][g_l], tile[2 * p + 1][g_l]);
        *(__half2*)&g_featT[(size_t)(gx + g_l) * BATCH + 2 * p] = h;
    }
}

// ---------------------------------------------------------------------------
// K2: gather-sum (best-measured config). One warp per unit; each LDG.128
// covers two gene rows (half-warp per gene, 16B batch slice per lane);
// batches of 4 LDG.128 in flight. half2 accumulate, fp32 flush every 8
// genes; cross-half shfl_xor(16); STG.128 streaming epilogue.
// ---------------------------------------------------------------------------
__global__ void __launch_bounds__(256, 5) ppi_gather_kernel(
    const int*   __restrict__ ppi,     // int32 (JAX x64-disabled)
    const float* __restrict__ kern,
    const float* __restrict__ bias,
    float*       __restrict__ out)
{
    __shared__ float tile[8][BATCH + 4];

    const int lane   = threadIdx.x & 31;
    const int hlane  = lane & 15;                 // batch-slice owner (16B)
    const int hsel   = lane >> 4;                 // 0: even gene, 1: odd gene
    const int warp   = threadIdx.x >> 5;
    const int u_base = blockIdx.x * 8;
    const int u      = u_base + warp;

    // Preamble: row byte-offset of ppi[u][lane] (row = 256B) + unit params.
    const int myoff = ppi[(size_t)u * DEG + lane] << 8;
    const float kv  = kern[u];
    const float bv  = bias[u];
    const char* base = (const char*)g_featT + hlane * 16;

    float facc[8];
#pragma unroll
    for (int j = 0; j < 8; j++) facc[j] = 0.f;

#pragma unroll
    for (int half = 0; half < 2; half++) {        // 2 flush periods x 16 genes
        __half2 hacc[4];
#pragma unroll
        for (int j = 0; j < 4; j++) hacc[j] = __floats2half2_rn(0.f, 0.f);

#pragma unroll
        for (int bb = 0; bb < 2; bb++) {          // 2 batches of 4 LDG.128
            uint4 raw[4];
#pragma unroll
            for (int q = 0; q < 4; q++) {
                const int it  = half * 8 + bb * 4 + q;          // 0..15
                const int off = __shfl_sync(0xffffffffu, myoff, 2 * it + hsel);
                raw[q] = *(const uint4*)(base + off);
            }
#pragma unroll
            for (int q = 0; q < 4; q++) {
                hacc[0] = __hadd2(hacc[0], *(const __half2*)&raw[q].x);
                hacc[1] = __hadd2(hacc[1], *(const __half2*)&raw[q].y);
                hacc[2] = __hadd2(hacc[2], *(const __half2*)&raw[q].z);
                hacc[3] = __hadd2(hacc[3], *(const __half2*)&raw[q].w);
            }
        }
#pragma unroll
        for (int j = 0; j < 4; j++) {             // fp32 flush
            const float2 f = __half22float2(hacc[j]);
            facc[2 * j]     += f.x;
            facc[2 * j + 1] += f.y;
        }
    }

    // Combine the two half-warps (same batch slice, disjoint gene subsets).
#pragma unroll
    for (int j = 0; j < 8; j++)
        facc[j] += __shfl_xor_sync(0xffffffffu, facc[j], 16);

    if (lane < 16) {                              // conflict-free 512B row
        float r[8];
#pragma unroll
        for (int j = 0; j < 8; j++)
            r[j] = tanhf(fmaf(facc[j], kv, bv));
        *(float4*)&tile[warp][hlane * 8]     = make_float4(r[0], r[1], r[2], r[3]);
        *(float4*)&tile[warp][hlane * 8 + 4] = make_float4(r[4], r[5], r[6], r[7]);
    }
    __syncthreads();

    // STG.128 streaming epilogue: thread t packs units [4q, 4q+4) of batch
    // row b into one float4. smem reads conflict-free (bank = (16q+4j+b)%32
    // spans all 32 banks across the warp); stores 16B-aligned (u_base%8==0).
    {
        const int t = threadIdx.x;                // 256 threads, 256 tasks
        const int b = t >> 1;
        const int q = t & 1;
        const float4 v = make_float4(tile[q * 4 + 0][b], tile[q * 4 + 1][b],
                                     tile[q * 4 + 2][b], tile[q * 4 + 3][b]);
        __stcs((float4*)&out[(size_t)b * UNITS + u_base + q * 4], v);
    }
}

// ---------------------------------------------------------------------------
extern "C" void kernel_launch(void* const* d_in, const int* in_sizes, int n_in,
                              void* d_out, int out_size) {
    const float* feature = (const float*)d_in[0];
    const int*   ppi     = (const int*)d_in[1];
    const float* kern    = (const float*)d_in[2];
    const float* bias    = (const float*)d_in[3];
    float*       out     = (float*)d_out;

    transpose_abs_kernel<<<N_GENES / 32, 256>>>(feature);        // 625 CTAs
    ppi_gather_kernel<<<UNITS / 8, 256>>>(ppi, kern, bias, out); // 1250 CTAs
}

// round 16
// speedup vs baseline: 1.0194x; 1.0194x over previous
#include <cuda_runtime.h>
#include <cuda_fp16.h>
#include <cstdint>

#define N_GENES 20000
#define UNITS   10000
#define DEG     32
#define BATCH   128

// |feature| transposed to [gene][batch] in fp16: 5.12 MB, L2-resident.
// Row = 256B; each (unit, deg) gather reads one full row, coalesced.
// The gather sits at the L2 slice-service floor (10.8-11.2us node,
// invariant across R4-R15). Sub-fp16 storage fails the 1e-3 error gate.
__device__ __half g_featT[(size_t)N_GENES * BATCH];

// HW tanh (MUFU.TANH, sm_75+): single-instruction approx, err ~1e-4 class.
__device__ __forceinline__ float tanh_fast(float x) {
    float y;
    asm("tanh.approx.f32 %0, %1;" : "=f"(y) : "f"(x));
    return y;
}

// ---------------------------------------------------------------------------
// K1: transpose + fabs + fp16.  feature [128, 20000] -> featT [N, B].
// One CTA per 32-gene column block covering the FULL batch: each gene's
// 256B featT row is written contiguously by one 64-thread group.
// ---------------------------------------------------------------------------
__global__ void __launch_bounds__(256) transpose_abs_kernel(
    const float* __restrict__ feature)
{
    __shared__ float tile[BATCH][33];            // tile[batch][gene], 16.9 KB
    const int gx  = blockIdx.x * 32;
    const int tx  = threadIdx.x & 31;            // gene within block
    const int row = threadIdx.x >> 5;            // batch row 0..7

#pragma unroll
    for (int k = 0; k < BATCH; k += 8)
        tile[row + k][tx] = fabsf(feature[(size_t)(row + k) * N_GENES + (gx + tx)]);
    __syncthreads();

    // 64 consecutive threads emit one contiguous 256B gene row.
#pragma unroll
    for (int tt = 0; tt < 8; tt++) {
        const int task = tt * 256 + threadIdx.x;
        const int g_l  = task >> 6;              // 0..31
        const int p    = task & 63;              // batch pair
        const __half2 h = __floats2half2_rn(tile[2 * p][g_l], tile[2 * p + 1][g_l]);
        *(__half2*)&g_featT[(size_t)(gx + g_l) * BATCH + 2 * p] = h;
    }
}

// ---------------------------------------------------------------------------
// K2: gather-sum (best-measured config). One warp per unit; each LDG.128
// covers two gene rows (half-warp per gene, 16B batch slice per lane);
// batches of 4 LDG.128 in flight. half2 accumulate, fp32 flush every 8
// genes; cross-half shfl_xor(16); MUFU.TANH + STG.128 streaming epilogue.
// ---------------------------------------------------------------------------
__global__ void __launch_bounds__(256, 5) ppi_gather_kernel(
    const int*   __restrict__ ppi,     // int32 (JAX x64-disabled)
    const float* __restrict__ kern,
    const float* __restrict__ bias,
    float*       __restrict__ out)
{
    __shared__ float tile[8][BATCH + 4];

    const int lane   = threadIdx.x & 31;
    const int hlane  = lane & 15;                 // batch-slice owner (16B)
    const int hsel   = lane >> 4;                 // 0: even gene, 1: odd gene
    const int warp   = threadIdx.x >> 5;
    const int u_base = blockIdx.x * 8;
    const int u      = u_base + warp;

    // Preamble: row byte-offset of ppi[u][lane] (row = 256B) + unit params.
    const int myoff = ppi[(size_t)u * DEG + lane] << 8;
    const float kv  = kern[u];
    const float bv  = bias[u];
    const char* base = (const char*)g_featT + hlane * 16;

    float facc[8];
#pragma unroll
    for (int j = 0; j < 8; j++) facc[j] = 0.f;

#pragma unroll
    for (int half = 0; half < 2; half++) {        // 2 flush periods x 16 genes
        __half2 hacc[4];
#pragma unroll
        for (int j = 0; j < 4; j++) hacc[j] = __floats2half2_rn(0.f, 0.f);

#pragma unroll
        for (int bb = 0; bb < 2; bb++) {          // 2 batches of 4 LDG.128
            uint4 raw[4];
#pragma unroll
            for (int q = 0; q < 4; q++) {
                const int it  = half * 8 + bb * 4 + q;          // 0..15
                const int off = __shfl_sync(0xffffffffu, myoff, 2 * it + hsel);
                raw[q] = *(const uint4*)(base + off);
            }
#pragma unroll
            for (int q = 0; q < 4; q++) {
                hacc[0] = __hadd2(hacc[0], *(const __half2*)&raw[q].x);
                hacc[1] = __hadd2(hacc[1], *(const __half2*)&raw[q].y);
                hacc[2] = __hadd2(hacc[2], *(const __half2*)&raw[q].z);
                hacc[3] = __hadd2(hacc[3], *(const __half2*)&raw[q].w);
            }
        }
#pragma unroll
        for (int j = 0; j < 4; j++) {             // fp32 flush
            const float2 f = __half22float2(hacc[j]);
            facc[2 * j]     += f.x;
            facc[2 * j + 1] += f.y;
        }
    }

    // Combine the two half-warps (same batch slice, disjoint gene subsets).
#pragma unroll
    for (int j = 0; j < 8; j++)
        facc[j] += __shfl_xor_sync(0xffffffffu, facc[j], 16);

    if (lane < 16) {                              // conflict-free 512B row
        float r[8];
#pragma unroll
        for (int j = 0; j < 8; j++)
            r[j] = tanh_fast(fmaf(facc[j], kv, bv));
        *(float4*)&tile[warp][hlane * 8]     = make_float4(r[0], r[1], r[2], r[3]);
        *(float4*)&tile[warp][hlane * 8 + 4] = make_float4(r[4], r[5], r[6], r[7]);
    }
    __syncthreads();

    // STG.128 streaming epilogue: thread t packs units [4q, 4q+4) of batch
    // row b into one float4. smem reads conflict-free (bank = (16q+4j+b)%32
    // spans all 32 banks across the warp); stores 16B-aligned (u_base%8==0).
    {
        const int t = threadIdx.x;                // 256 threads, 256 tasks
        const int b = t >> 1;
        const int q = t & 1;
        const float4 v = make_float4(tile[q * 4 + 0][b], tile[q * 4 + 1][b],
                                     tile[q * 4 + 2][b], tile[q * 4 + 3][b]);
        __stcs((float4*)&out[(size_t)b * UNITS + u_base + q * 4], v);
    }
}

// ---------------------------------------------------------------------------
extern "C" void kernel_launch(void* const* d_in, const int* in_sizes, int n_in,
                              void* d_out, int out_size) {
    const float* feature = (const float*)d_in[0];
    const int*   ppi     = (const int*)d_in[1];
    const float* kern    = (const float*)d_in[2];
    const float* bias    = (const float*)d_in[3];
    float*       out     = (float*)d_out;

    transpose_abs_kernel<<<N_GENES / 32, 256>>>(feature);        // 625 CTAs
    ppi_gather_kernel<<<UNITS / 8, 256>>>(ppi, kern, bias, out); // 1250 CTAs
}